// round 6
// baseline (speedup 1.0000x reference)
#include <cuda_runtime.h>
#include <cuda_bf16.h>
#include <cuda_fp16.h>
#include <cstdint>

#define NNODE 20000
#define MPAD  20224
#define FEAT  512
#define EMAX  320000
#define FF    (FEAT*FEAT)
#define BN_EPS 1e-5f

#if defined(__CUDA_ARCH_FEAT_SM103_ALL) || defined(__CUDA_ARCH_FEAT_SM100_ALL) || defined(__CUDA_ARCH_FEAT_SM101_ALL)
#define HAS_TCGEN05 1
#else
#define HAS_TCGEN05 0
#endif

// ================= device scratch (static, no allocs) =================
__device__ __nv_bfloat16 g_Ap_hi[(size_t)MPAD * 2048];
__device__ __nv_bfloat16 g_Ap_lo[(size_t)MPAD * 2048];
__device__ __nv_bfloat16 g_Ad_hi[(size_t)MPAD * 1024];
__device__ __nv_bfloat16 g_Ad_lo[(size_t)MPAD * 1024];
__device__ __nv_bfloat16 g_Bp_hi[2][512 * 2048];
__device__ __nv_bfloat16 g_Bp_lo[2][512 * 2048];
__device__ __nv_bfloat16 g_Bd_hi[2][512 * 1024];
__device__ __nv_bfloat16 g_Bd_lo[2][512 * 1024];
__device__ __nv_bfloat16 g_Bq_hi[2][512 * 512];
__device__ __nv_bfloat16 g_Bq_lo[2][512 * 512];
__device__ __half g_hd16[(size_t)NNODE * FEAT];
__device__ __half g_hp16[(size_t)NNODE * FEAT];
__device__ float g_biasP[2][FEAT];
__device__ float g_biasD[2][FEAT];
__device__ float g_rawd[(size_t)NNODE * FEAT];
__device__ float g_rawp[(size_t)NNODE * FEAT];
__device__ float g_bnstat[4 * FEAT];  // [sum_d, sumsq_d, sum_p, sumsq_p]
__device__ int   g_cnt[4 * NNODE];
__device__ int   g_cur[4 * NNODE];
__device__ int   g_off[4 * (NNODE + 1)];
__device__ int   g_adj[4 * EMAX];

// ================= PTX helpers =================
__device__ __forceinline__ uint32_t smem_to_u32(const void* p) {
    uint32_t a;
    asm("{ .reg .u64 t; cvta.to.shared.u64 t, %1; cvt.u32.u64 %0, t; }" : "=r"(a) : "l"(p));
    return a;
}
__device__ __forceinline__ uint32_t elect_one_pred() {
    uint32_t pred;
    asm volatile("{\n\t.reg .pred p;\n\telect.sync _|p, 0xFFFFFFFF;\n\tselp.b32 %0, 1, 0, p;\n\t}" : "=r"(pred));
    return pred;
}
#define SMEM_SWIZZLE_64B(o) ((o) ^ (((o) >> 3) & 0x30))
// SW64 descriptor: layout=4, version=1, SBO=32 (512B atom stride), LBO=1 (16B)
static constexpr uint64_t SMEM_DESC_BASE_SW64 =
    (uint64_t(4) << 61) | (uint64_t(1) << 46) | (uint64_t(32) << 32) | (uint64_t(1) << 16);
#define MAKE_SMEM_DESC64(base) (SMEM_DESC_BASE_SW64 | ((uint64_t)((base) >> 4) & 0x3FFF))

#define CP_ASYNC16(dst, src) \
    asm volatile("cp.async.cg.shared.global [%0], [%1], 16;" :: "r"(dst), "l"(src) : "memory")
#define CP_COMMIT() asm volatile("cp.async.commit_group;" ::: "memory")
#define CP_WAIT1() asm volatile("cp.async.wait_group 1;" ::: "memory")
#define CP_WAIT0() asm volatile("cp.async.wait_group 0;" ::: "memory")

#if HAS_TCGEN05
#define TCGEN05_ALLOC(sm, n) \
    asm volatile("tcgen05.alloc.cta_group::1.sync.aligned.shared::cta.b32 [%0], %1;" \
                 :: "r"((uint32_t)(sm)), "r"((uint32_t)(n)) : "memory")
#define TCGEN05_DEALLOC(t, n) \
    asm volatile("tcgen05.dealloc.cta_group::1.sync.aligned.b32 %0, %1;" :: "r"(t), "r"((uint32_t)(n)))
#define TCGEN05_RELINQ() \
    asm volatile("tcgen05.relinquish_alloc_permit.cta_group::1.sync.aligned;")
#define TCGEN05_COMMIT(mb) \
    asm volatile("tcgen05.commit.cta_group::1.mbarrier::arrive::one.shared::cluster.b64 [%0];" \
                 :: "r"((uint32_t)(mb)) : "memory")
#define TCGEN05_WAIT_LD()  asm volatile("tcgen05.wait::ld.sync.aligned;" ::: "memory")
#define TCGEN05_FENCE_BEFORE() asm volatile("tcgen05.fence::before_thread_sync;" ::: "memory")
#define TCGEN05_FENCE_AFTER()  asm volatile("tcgen05.fence::after_thread_sync;" ::: "memory")
#define FENCE_ASYNC_SHARED() asm volatile("fence.proxy.async.shared::cta;" ::: "memory")
#define MBARRIER_INIT(mb, c) \
    asm volatile("mbarrier.init.shared.b64 [%0], %1;" :: "r"((uint32_t)(mb)), "r"((uint32_t)(c)) : "memory")
#define MBARRIER_INVAL(mb) \
    asm volatile("mbarrier.inval.shared.b64 [%0];" :: "r"((uint32_t)(mb)) : "memory")
#define MBARRIER_WAIT_PARITY(mb, ph) do { \
    uint32_t _mb = (uint32_t)(mb), _ph = (uint32_t)(ph), _done; \
    asm volatile("{\n\t.reg .pred p;\n\tmbarrier.try_wait.parity.acquire.cta.shared::cta.b64 p, [%1], %2;\n\tselp.b32 %0, 1, 0, p;\n\t}" \
        : "=r"(_done) : "r"(_mb), "r"(_ph) : "memory"); \
    if (!_done) { \
        asm volatile("{\n\t.reg .pred P1;\n\tWL_%=: \n\tmbarrier.try_wait.parity.acquire.cta.shared::cta.b64 P1, [%0], %1, 0x989680;\n\t@P1 bra.uni WD_%=;\n\tbra.uni WL_%=;\n\tWD_%=: \n\t}" \
            :: "r"(_mb), "r"(_ph) : "memory"); \
    } \
} while (0)

#define TCGEN05_LD_X32(r, addr) \
    asm volatile("tcgen05.ld.sync.aligned.32x32b.x32.b32 " \
        "{%0, %1, %2, %3, %4, %5, %6, %7, %8, %9, %10, %11, %12, %13, %14, %15, " \
        " %16, %17, %18, %19, %20, %21, %22, %23, %24, %25, %26, %27, %28, %29, %30, %31}, [%32];" \
        : "=r"((r)[0]), "=r"((r)[1]), "=r"((r)[2]), "=r"((r)[3]), "=r"((r)[4]), "=r"((r)[5]), "=r"((r)[6]), "=r"((r)[7]), \
          "=r"((r)[8]), "=r"((r)[9]), "=r"((r)[10]), "=r"((r)[11]), "=r"((r)[12]), "=r"((r)[13]), "=r"((r)[14]), "=r"((r)[15]), \
          "=r"((r)[16]), "=r"((r)[17]), "=r"((r)[18]), "=r"((r)[19]), "=r"((r)[20]), "=r"((r)[21]), "=r"((r)[22]), "=r"((r)[23]), \
          "=r"((r)[24]), "=r"((r)[25]), "=r"((r)[26]), "=r"((r)[27]), "=r"((r)[28]), "=r"((r)[29]), "=r"((r)[30]), "=r"((r)[31]) \
        : "r"(addr))

__device__ __forceinline__ void mma_bf16_ss(uint32_t d_tmem, uint64_t a_desc, uint64_t b_desc,
                                            uint32_t idesc, uint32_t enable) {
    asm volatile(
        "{\n\t.reg .pred p;\n\tsetp.ne.u32 p, %5, 0;\n\t"
        "tcgen05.mma.cta_group::1.kind::f16 [%0], %1, %2, %3, {%4, %4, %4, %4}, p;\n\t}"
        :: "r"(d_tmem), "l"(a_desc), "l"(b_desc), "r"(idesc), "r"(0u), "r"(enable)
        : "memory");
}
#endif // HAS_TCGEN05

__device__ __forceinline__ void split1(float v, __nv_bfloat16& h, __nv_bfloat16& l) {
    h = __float2bfloat16(v);
    l = __float2bfloat16(v - __bfloat162float(h));
}

// ================= CSR build =================
__global__ void zero_cnt_kernel() {
    int i = blockIdx.x * blockDim.x + threadIdx.x;
    if (i < 4 * NNODE) g_cnt[i] = 0;
}
__global__ void hist_kernel(const int* __restrict__ a_src, const int* __restrict__ a_dst,
                            const int* __restrict__ i_src, const int* __restrict__ i_dst, int E) {
    int i = blockIdx.x * blockDim.x + threadIdx.x;
    if (i >= 4 * E) return;
    int w = i / E, e = i - w * E;
    int k = (w == 0) ? a_dst[e] : (w == 1) ? a_src[e] : (w == 2) ? i_dst[e] : i_src[e];
    atomicAdd(&g_cnt[w * NNODE + k], 1);
}
__global__ void scan_kernel() {
    int c = blockIdx.x;
    __shared__ int sh[1024];
    __shared__ int carry_sh;
    int tid = threadIdx.x;
    if (tid == 0) { carry_sh = 0; g_off[c * (NNODE + 1)] = 0; }
    __syncthreads();
    for (int base = 0; base < NNODE; base += 1024) {
        int i = base + tid;
        int v = (i < NNODE) ? g_cnt[c * NNODE + i] : 0;
        sh[tid] = v;
        __syncthreads();
        #pragma unroll
        for (int d = 1; d < 1024; d <<= 1) {
            int t = (tid >= d) ? sh[tid - d] : 0;
            __syncthreads();
            sh[tid] += t;
            __syncthreads();
        }
        int incl = sh[tid];
        int carry = carry_sh;
        __syncthreads();
        if (i < NNODE) {
            g_off[c * (NNODE + 1) + i + 1] = carry + incl;
            g_cur[c * NNODE + i] = carry + incl - v;
        }
        if (tid == 1023) carry_sh = carry + sh[1023];
        __syncthreads();
    }
}
__global__ void fill_kernel(const int* __restrict__ a_src, const int* __restrict__ a_dst,
                            const int* __restrict__ i_src, const int* __restrict__ i_dst, int E) {
    int i = blockIdx.x * blockDim.x + threadIdx.x;
    if (i >= 4 * E) return;
    int w = i / E, e = i - w * E;
    int k = (w == 0) ? a_dst[e] : (w == 1) ? a_src[e] : (w == 2) ? i_dst[e] : i_src[e];
    int v = (w == 0) ? a_src[e] : (w == 1) ? a_dst[e] : (w == 2) ? i_src[e] : i_dst[e];
    int pos = atomicAdd(&g_cur[w * NNODE + k], 1);
    g_adj[w * E + pos] = v;
}

// ========== fused 4-way segment-mean gather from fp16 sources ==========
__global__ void gather4_kernel(const __half* __restrict__ srcD, const __half* __restrict__ srcP,
                               __nv_bfloat16* __restrict__ ApH, __nv_bfloat16* __restrict__ ApL,
                               __nv_bfloat16* __restrict__ AdH, __nv_bfloat16* __restrict__ AdL,
                               int E) {
    int c = blockIdx.y;
    const __half* src = (c == 0) ? srcD : srcP;
    __nv_bfloat16* hi;
    __nv_bfloat16* lo;
    int lda, coff;
    if (c == 1) { hi = AdH; lo = AdL; lda = 1024; coff = 512; }
    else {
        hi = ApH; lo = ApL; lda = 2048;
        coff = (c == 0) ? 512 : (c == 2) ? 1024 : 1536;
    }
    int n = blockIdx.x;
    int t = threadIdx.x;            // 0..63, 8 halves each (16B)
    int s = g_off[c * (NNODE + 1) + n];
    int e = g_off[c * (NNODE + 1) + n + 1];
    const int* adj = g_adj + (size_t)c * E;
    float acc[8] = {0.f, 0.f, 0.f, 0.f, 0.f, 0.f, 0.f, 0.f};
    int j = s;
    for (; j + 3 < e; j += 4) {
        int r0 = adj[j], r1 = adj[j + 1], r2 = adj[j + 2], r3 = adj[j + 3];
        uint4 v0 = *(const uint4*)(src + (size_t)r0 * FEAT + t * 8);
        uint4 v1 = *(const uint4*)(src + (size_t)r1 * FEAT + t * 8);
        uint4 v2 = *(const uint4*)(src + (size_t)r2 * FEAT + t * 8);
        uint4 v3 = *(const uint4*)(src + (size_t)r3 * FEAT + t * 8);
        const uint4* vs[4] = {&v0, &v1, &v2, &v3};
        #pragma unroll
        for (int q = 0; q < 4; q++) {
            const __half2* h2 = (const __half2*)vs[q];
            #pragma unroll
            for (int p = 0; p < 4; p++) {
                float2 f = __half22float2(h2[p]);
                acc[2 * p] += f.x; acc[2 * p + 1] += f.y;
            }
        }
    }
    for (; j < e; j++) {
        int r0 = adj[j];
        uint4 v0 = *(const uint4*)(src + (size_t)r0 * FEAT + t * 8);
        const __half2* h2 = (const __half2*)&v0;
        #pragma unroll
        for (int p = 0; p < 4; p++) {
            float2 f = __half22float2(h2[p]);
            acc[2 * p] += f.x; acc[2 * p + 1] += f.y;
        }
    }
    float inv = (e > s) ? 1.0f / (float)(e - s) : 0.0f;
    __nv_bfloat16 h[8], l[8];
    #pragma unroll
    for (int q = 0; q < 8; q++) split1(acc[q] * inv, h[q], l[q]);
    size_t o = (size_t)n * lda + coff + t * 8;
    *(uint4*)(hi + o) = *(uint4*)&h[0];
    *(uint4*)(lo + o) = *(uint4*)&l[0];
}

// ========== merged split of both fp32 inputs ==========
__global__ void split2_kernel(const float* __restrict__ h_p, const float* __restrict__ h_d,
                              __nv_bfloat16* __restrict__ ApH, __nv_bfloat16* __restrict__ ApL,
                              __nv_bfloat16* __restrict__ AdH, __nv_bfloat16* __restrict__ AdL,
                              __half* __restrict__ hp16, __half* __restrict__ hd16) {
    size_t idx = (size_t)blockIdx.x * blockDim.x + threadIdx.x;
    if (idx >= (size_t)NNODE * FEAT) return;
    int row = (int)(idx >> 9), col = (int)(idx & 511);
    const float* src = blockIdx.y ? h_d : h_p;
    __nv_bfloat16* hi = blockIdx.y ? AdH : ApH;
    __nv_bfloat16* lo = blockIdx.y ? AdL : ApL;
    __half* f16 = blockIdx.y ? hd16 : hp16;
    int lda = blockIdx.y ? 1024 : 2048;
    float v = src[idx];
    __nv_bfloat16 h, l;
    split1(v, h, l);
    size_t o = (size_t)row * lda + col;
    hi[o] = h; lo[o] = l;
    f16[idx] = __float2half(v);
}

// ========== mega weight prep: all layers + projections, one launch ==========
__global__ void wprep_all_kernel(const float* __restrict__ Ws1, const float* __restrict__ Wn1,
                                 const float* __restrict__ b1,
                                 const float* __restrict__ Ws2, const float* __restrict__ Wn2,
                                 const float* __restrict__ b2,
                                 const float* __restrict__ pWd, const float* __restrict__ pWp) {
    int i = blockIdx.x * blockDim.x + threadIdx.x;
    if (i >= FF) return;
    int which = blockIdx.y;     // 0: p-l1, 1: d-l1, 2: p-l2, 3: d-l2, 4: q_d, 5: q_p
    int n = i & 511, k = i >> 9;
    __nv_bfloat16 h, l;
    if (which == 0 || which == 2) {
        int li = which >> 1;
        const float* Ws = li ? Ws2 : Ws1;
        const float* Wn = li ? Wn2 : Wn1;
        const float* b  = li ? b2 : b1;
        float v0 = Ws[k * 512 + n] + Ws[2 * FF + k * 512 + n] + Ws[3 * FF + k * 512 + n];
        float v1 = Wn[0 * FF + k * 512 + n];
        float v2 = Wn[2 * FF + k * 512 + n];
        float v3 = Wn[3 * FF + k * 512 + n];
        size_t base = (size_t)n * 2048;
        split1(v0, h, l); g_Bp_hi[li][base + k] = h;        g_Bp_lo[li][base + k] = l;
        split1(v1, h, l); g_Bp_hi[li][base + 512 + k] = h;  g_Bp_lo[li][base + 512 + k] = l;
        split1(v2, h, l); g_Bp_hi[li][base + 1024 + k] = h; g_Bp_lo[li][base + 1024 + k] = l;
        split1(v3, h, l); g_Bp_hi[li][base + 1536 + k] = h; g_Bp_lo[li][base + 1536 + k] = l;
        if (i < 512) g_biasP[li][i] = b[i] + b[1024 + i] + b[1536 + i];
    } else if (which == 1 || which == 3) {
        int li = which >> 1;
        const float* Ws = li ? Ws2 : Ws1;
        const float* Wn = li ? Wn2 : Wn1;
        const float* b  = li ? b2 : b1;
        float v0 = Ws[FF + k * 512 + n];
        float v1 = Wn[FF + k * 512 + n];
        size_t base = (size_t)n * 1024;
        split1(v0, h, l); g_Bd_hi[li][base + k] = h;       g_Bd_lo[li][base + k] = l;
        split1(v1, h, l); g_Bd_hi[li][base + 512 + k] = h; g_Bd_lo[li][base + 512 + k] = l;
        if (i < 512) g_biasD[li][i] = b[512 + i];
    } else {
        int q = which - 4;
        const float* W = q ? pWp : pWd;
        split1(W[k * 512 + n], h, l);
        g_Bq_hi[q][n * 512 + k] = h;
        g_Bq_lo[q][n * 512 + k] = l;
    }
}

// ================= paired pipelined tcgen05 bf16-split GEMM, M=256 x N=256, KC=32, SW64 ===
struct GPair {
    const __nv_bfloat16 *Ah0, *Al0, *Bh0, *Bl0; const float* bias0; float* C0; int lda0, ldb0, K0;
    const __nv_bfloat16 *Ah1, *Al1, *Bh1, *Bl1; const float* bias1; float* C1; int lda1, ldb1, K1;
};
#define STAGE_BYTES 65536   // Ah 16K | Al 16K | Bh 16K | Bl 16K
#define GEMM_SMEM (1024 + 2 * STAGE_BYTES)
__global__ __launch_bounds__(128)
void mma_gemm_pair(const GPair gp, int M) {
    const __nv_bfloat16* Ahi = blockIdx.z ? gp.Ah1 : gp.Ah0;
    const __nv_bfloat16* Alo = blockIdx.z ? gp.Al1 : gp.Al0;
    const __nv_bfloat16* Bhi = blockIdx.z ? gp.Bh1 : gp.Bh0;
    const __nv_bfloat16* Blo = blockIdx.z ? gp.Bl1 : gp.Bl0;
    const float* bias = blockIdx.z ? gp.bias1 : gp.bias0;
    float* C = blockIdx.z ? gp.C1 : gp.C0;
    const int lda = blockIdx.z ? gp.lda1 : gp.lda0;
    const int ldb = blockIdx.z ? gp.ldb1 : gp.ldb0;
    const int Ktot = blockIdx.z ? gp.K1 : gp.K0;
#if HAS_TCGEN05
    extern __shared__ char smem[];
    uint32_t sb = smem_to_u32(smem);
    const int tid = threadIdx.x;
    const int wid = tid >> 5, lid = tid & 31;
    const int m0 = blockIdx.y * 256, n0 = blockIdx.x * 256;

    if (wid == 0) { TCGEN05_ALLOC(sb, 512); TCGEN05_RELINQ(); }
    if (tid == 0) MBARRIER_INIT(sb + 8, 1);
    __syncthreads();
    uint32_t tbase;
    asm volatile("ld.shared.b32 %0, [%1];" : "=r"(tbase) : "r"(sb));

    const uint32_t idesc = 0x8400490u;   // F32 acc, bf16, M=128, N=256
    const int nst = Ktot >> 5;           // KC = 32

    auto issue_loads = [&](int s) {
        int k0 = s << 5;
        uint32_t base = sb + 1024 + (uint32_t)(s & 1) * STAGE_BYTES;
        // A hi/lo: 256 rows x 64B = 1024 16B-chunks each; 8 per thread
        #pragma unroll
        for (int c = 0; c < 8; c++) {
            int chunk = c * 128 + tid;
            int row = chunk >> 2, ch = chunk & 3;
            uint32_t sw = SMEM_SWIZZLE_64B((uint32_t)(row * 64 + ch * 16));
            size_t ga = (size_t)(m0 + row) * lda + k0 + ch * 8;
            size_t gb = (size_t)(n0 + row) * ldb + k0 + ch * 8;
            CP_ASYNC16(base + sw, Ahi + ga);
            CP_ASYNC16(base + 16384 + sw, Alo + ga);
            CP_ASYNC16(base + 32768 + sw, Bhi + gb);
            CP_ASYNC16(base + 49152 + sw, Blo + gb);
        }
        CP_COMMIT();
    };

    issue_loads(0);
    for (int s = 0; s < nst; s++) {
        if (s >= 1) MBARRIER_WAIT_PARITY(sb + 8, (s - 1) & 1);
        if (s + 1 < nst) { issue_loads(s + 1); CP_WAIT1(); }
        else             { CP_WAIT0(); }
        __syncthreads();
        FENCE_ASYNC_SHARED();
        if (wid == 0 && elect_one_pred()) {
            uint32_t bufb = sb + 1024 + (uint32_t)(s & 1) * STAGE_BYTES;
            uint64_t dAh0 = MAKE_SMEM_DESC64(bufb);
            uint64_t dAh1 = MAKE_SMEM_DESC64(bufb + 8192);
            uint64_t dAl0 = MAKE_SMEM_DESC64(bufb + 16384);
            uint64_t dAl1 = MAKE_SMEM_DESC64(bufb + 24576);
            uint64_t dBh  = MAKE_SMEM_DESC64(bufb + 32768);
            uint64_t dBl  = MAKE_SMEM_DESC64(bufb + 49152);
            #pragma unroll
            for (int kk = 0; kk < 2; kk++) {
                uint64_t o = (uint64_t)(kk * 2);
                uint32_t en0 = !(s == 0 && kk == 0);
                mma_bf16_ss(tbase,       dAh0 + o, dBh + o, idesc, en0);
                mma_bf16_ss(tbase + 256, dAh1 + o, dBh + o, idesc, en0);
                mma_bf16_ss(tbase,       dAh0 + o, dBl + o, idesc, 1u);
                mma_bf16_ss(tbase + 256, dAh1 + o, dBl + o, idesc, 1u);
                mma_bf16_ss(tbase,       dAl0 + o, dBh + o, idesc, 1u);
                mma_bf16_ss(tbase + 256, dAl1 + o, dBh + o, idesc, 1u);
            }
            TCGEN05_COMMIT(sb + 8);
        }
    }
    MBARRIER_WAIT_PARITY(sb + 8, (nst - 1) & 1);
    TCGEN05_FENCE_AFTER();

    #pragma unroll
    for (int half = 0; half < 2; half++) {
        int gr = m0 + half * 128 + wid * 32 + lid;
        uint32_t dt = tbase + half * 256;
        #pragma unroll
        for (int base = 0; base < 256; base += 32) {
            uint32_t r[32];
            TCGEN05_LD_X32(r, dt + base);
            TCGEN05_WAIT_LD();
            if (gr < M) {
                float* cp = C + (size_t)gr * 512 + n0 + base;
                #pragma unroll
                for (int j = 0; j < 32; j += 4) {
                    float4 v;
                    v.x = __uint_as_float(r[j + 0]) + bias[n0 + base + j + 0];
                    v.y = __uint_as_float(r[j + 1]) + bias[n0 + base + j + 1];
                    v.z = __uint_as_float(r[j + 2]) + bias[n0 + base + j + 2];
                    v.w = __uint_as_float(r[j + 3]) + bias[n0 + base + j + 3];
                    *(float4*)(cp + j) = v;
                }
            }
        }
    }
    TCGEN05_FENCE_BEFORE();
    __syncthreads();
    if (tid == 0) MBARRIER_INVAL(sb + 8);
    __syncthreads();
    if (wid == 0) TCGEN05_DEALLOC(tbase, 512);
#else
    const int tid = threadIdx.x;
    const int m0 = blockIdx.y * 256, n0 = blockIdx.x * 256;
    for (int rc = tid; rc < 256 * 256; rc += blockDim.x) {
        int r = rc >> 8, c = rc & 255;
        int gr = m0 + r, gc = n0 + c;
        if (gr >= M) continue;
        const __nv_bfloat16* ah = Ahi + (size_t)gr * lda;
        const __nv_bfloat16* al = Alo + (size_t)gr * lda;
        const __nv_bfloat16* bh = Bhi + (size_t)gc * ldb;
        const __nv_bfloat16* bl = Blo + (size_t)gc * ldb;
        float acc = 0.f;
        for (int k = 0; k < Ktot; k++) {
            float ahv = __bfloat162float(ah[k]), alv = __bfloat162float(al[k]);
            float bhv = __bfloat162float(bh[k]), blv = __bfloat162float(bl[k]);
            acc += ahv * bhv + ahv * blv + alv * bhv;
        }
        C[(size_t)gr * 512 + gc] = acc + bias[gc];
    }
#endif
}

// ================= BatchNorm + ReLU (merged d+p) =================
__global__ void zero_stats_kernel() {
    int i = blockIdx.x * blockDim.x + threadIdx.x;
    if (i < 4 * FEAT) g_bnstat[i] = 0.f;
}
// grid (4, 64): bx 0-1 -> disease cols, 2-3 -> protein cols
__global__ void bn_reduce2_kernel(const float* __restrict__ xd, const float* __restrict__ xp) {
    int gcol = blockIdx.x * 256 + threadIdx.x;   // 0..1023
    int isP = gcol >= 512;
    int col = gcol & 511;
    const float* x = isP ? xp : xd;
    float s = 0.f, s2 = 0.f;
    for (int r = blockIdx.y; r < NNODE; r += gridDim.y) {
        float v = x[(size_t)r * FEAT + col];
        s += v; s2 += v * v;
    }
    int base = isP ? 1024 : 0;
    atomicAdd(&g_bnstat[base + col], s);
    atomicAdd(&g_bnstat[base + 512 + col], s2);
}
// grid (NW, 2): y=0 disease, y=1 protein
__global__ void bn_norm2_kernel(const float* __restrict__ rawd, const float* __restrict__ rawp,
                                __half* __restrict__ hd16, __half* __restrict__ hp16,
                                __nv_bfloat16* __restrict__ AdH, __nv_bfloat16* __restrict__ AdL,
                                __nv_bfloat16* __restrict__ ApH, __nv_bfloat16* __restrict__ ApL,
                                const float* __restrict__ gamma_l, const float* __restrict__ beta_l) {
    size_t idx = (size_t)blockIdx.x * blockDim.x + threadIdx.x;
    if (idx >= (size_t)NNODE * FEAT) return;
    int isP = blockIdx.y;
    int col = (int)(idx & (FEAT - 1));
    int row = (int)(idx >> 9);
    const float* raw = isP ? rawp : rawd;
    __half* f16 = isP ? hp16 : hd16;
    __nv_bfloat16* hi = isP ? ApH : AdH;
    __nv_bfloat16* lo = isP ? ApL : AdL;
    int lda = isP ? 2048 : 1024;
    int sbase = isP ? 1024 : 0;
    const float* gamma = gamma_l + isP * FEAT;
    const float* beta  = beta_l + isP * FEAT;
    float mean = g_bnstat[sbase + col] * (1.0f / NNODE);
    float var  = g_bnstat[sbase + 512 + col] * (1.0f / NNODE) - mean * mean;
    float sc = gamma[col] * rsqrtf(var + BN_EPS);
    float v = (raw[idx] - mean) * sc + beta[col];
    v = v > 0.f ? v : 0.f;
    f16[idx] = __float2half(v);
    __nv_bfloat16 h, l;
    split1(v, h, l);
    size_t o = (size_t)row * lda + col;
    hi[o] = h; lo[o] = l;
}

// ================= host orchestration =================
extern "C" void kernel_launch(void* const* d_in, const int* in_sizes, int n_in,
                              void* d_out, int out_size) {
    const float* h_d  = (const float*)d_in[0];
    const float* h_p  = (const float*)d_in[1];
    const float* Ws1  = (const float*)d_in[2];
    const float* Wn1  = (const float*)d_in[3];
    const float* b1   = (const float*)d_in[4];
    const float* Ws2  = (const float*)d_in[5];
    const float* Wn2  = (const float*)d_in[6];
    const float* b2   = (const float*)d_in[7];
    const float* gam  = (const float*)d_in[8];
    const float* bet  = (const float*)d_in[9];
    const float* pWd  = (const float*)d_in[10];
    const float* pbd  = (const float*)d_in[11];
    const float* pWp  = (const float*)d_in[12];
    const float* pbp  = (const float*)d_in[13];
    const int* a_src = (const int*)d_in[14];
    const int* a_dst = (const int*)d_in[15];
    const int* i_src = (const int*)d_in[16];
    const int* i_dst = (const int*)d_in[17];
    int E = in_sizes[14];

    float* out_d = (float*)d_out;
    float* out_p = out_d + (size_t)NNODE * FEAT;

    __nv_bfloat16 *ApH, *ApL, *AdH, *AdL, *BpH, *BpL, *BdH, *BdL, *BqH, *BqL;
    float *rawd, *rawp, *biasP, *biasD;
    __half *hd16, *hp16;
    cudaGetSymbolAddress((void**)&ApH, g_Ap_hi);
    cudaGetSymbolAddress((void**)&ApL, g_Ap_lo);
    cudaGetSymbolAddress((void**)&AdH, g_Ad_hi);
    cudaGetSymbolAddress((void**)&AdL, g_Ad_lo);
    cudaGetSymbolAddress((void**)&BpH, g_Bp_hi);
    cudaGetSymbolAddress((void**)&BpL, g_Bp_lo);
    cudaGetSymbolAddress((void**)&BdH, g_Bd_hi);
    cudaGetSymbolAddress((void**)&BdL, g_Bd_lo);
    cudaGetSymbolAddress((void**)&BqH, g_Bq_hi);
    cudaGetSymbolAddress((void**)&BqL, g_Bq_lo);
    cudaGetSymbolAddress((void**)&rawd, g_rawd);
    cudaGetSymbolAddress((void**)&rawp, g_rawp);
    cudaGetSymbolAddress((void**)&biasP, g_biasP);
    cudaGetSymbolAddress((void**)&biasD, g_biasD);
    cudaGetSymbolAddress((void**)&hd16, g_hd16);
    cudaGetSymbolAddress((void**)&hp16, g_hp16);

    cudaFuncSetAttribute(mma_gemm_pair, cudaFuncAttributeMaxDynamicSharedMemorySize, GEMM_SMEM);

    const int NW = (NNODE * FEAT + 255) / 256;
    const int MT = (NNODE + 255) / 256;               // 79
    const dim3 gpair(2, MT, 2);
    const dim3 g4(NNODE, 4);

    GPair lay[2];
    for (int li = 0; li < 2; li++) {
        lay[li].Ah0 = ApH; lay[li].Al0 = ApL;
        lay[li].Bh0 = BpH + (size_t)li * 512 * 2048; lay[li].Bl0 = BpL + (size_t)li * 512 * 2048;
        lay[li].bias0 = biasP + li * FEAT; lay[li].C0 = rawp;
        lay[li].lda0 = 2048; lay[li].ldb0 = 2048; lay[li].K0 = 2048;
        lay[li].Ah1 = AdH; lay[li].Al1 = AdL;
        lay[li].Bh1 = BdH + (size_t)li * 512 * 1024; lay[li].Bl1 = BdL + (size_t)li * 512 * 1024;
        lay[li].bias1 = biasD + li * FEAT; lay[li].C1 = rawd;
        lay[li].lda1 = 1024; lay[li].ldb1 = 1024; lay[li].K1 = 1024;
    }
    GPair proj;
    proj.Ah0 = AdH; proj.Al0 = AdL; proj.Bh0 = BqH; proj.Bl0 = BqL;
    proj.bias0 = pbd; proj.C0 = out_d; proj.lda0 = 1024; proj.ldb0 = 512; proj.K0 = 512;
    proj.Ah1 = ApH; proj.Al1 = ApL; proj.Bh1 = BqH + FF; proj.Bl1 = BqL + FF;
    proj.bias1 = pbp; proj.C1 = out_p; proj.lda1 = 2048; proj.ldb1 = 512; proj.K1 = 512;

    // ---- prep (independent of edges) ----
    wprep_all_kernel<<<dim3((FF + 255) / 256, 6), 256>>>(Ws1, Wn1, b1, Ws2, Wn2, b2, pWd, pWp);
    split2_kernel<<<dim3(NW, 2), 256>>>(h_p, h_d, ApH, ApL, AdH, AdL, hp16, hd16);

    // ---- CSR build ----
    zero_cnt_kernel<<<(4 * NNODE + 255) / 256, 256>>>();
    hist_kernel<<<(4 * E + 255) / 256, 256>>>(a_src, a_dst, i_src, i_dst, E);
    scan_kernel<<<4, 1024>>>();
    fill_kernel<<<(4 * E + 255) / 256, 256>>>(a_src, a_dst, i_src, i_dst, E);

    // ---- layers ----
    for (int li = 0; li < 2; li++) {
        gather4_kernel<<<g4, 64>>>(hd16, hp16, ApH, ApL, AdH, AdL, E);
        mma_gemm_pair<<<gpair, 128, GEMM_SMEM>>>(lay[li], NNODE);
        zero_stats_kernel<<<8, 256>>>();
        bn_reduce2_kernel<<<dim3(4, 64), 256>>>(rawd, rawp);
        bn_norm2_kernel<<<dim3(NW, 2), 256>>>(rawd, rawp, hd16, hp16, AdH, AdL, ApH, ApL,
                                              gam + li * 2 * FEAT, bet + li * 2 * FEAT);
    }

    // ---- projections ----
    mma_gemm_pair<<<gpair, 128, GEMM_SMEM>>>(proj, NNODE);
}

// round 8
// speedup vs baseline: 1.1746x; 1.1746x over previous
#include <cuda_runtime.h>
#include <cuda_bf16.h>
#include <cuda_fp16.h>
#include <cstdint>

#define NNODE 20000
#define MPAD  20224
#define FEAT  512
#define EMAX  320000
#define FF    (FEAT*FEAT)
#define BN_EPS 1e-5f

#if defined(__CUDA_ARCH_FEAT_SM103_ALL) || defined(__CUDA_ARCH_FEAT_SM100_ALL) || defined(__CUDA_ARCH_FEAT_SM101_ALL)
#define HAS_TCGEN05 1
#else
#define HAS_TCGEN05 0
#endif

// ================= device scratch (static, no allocs) =================
// A matrices: fp16, self slot cols [0,512) doubles as gather source
__device__ __half g_Ap[(size_t)MPAD * 2048];
__device__ __half g_Ad[(size_t)MPAD * 1024];
// B matrices: fp16 hi/lo split, [n, k] layout
__device__ __half g_Bp_hi[2][512 * 2048];
__device__ __half g_Bp_lo[2][512 * 2048];
__device__ __half g_Bd_hi[2][512 * 1024];
__device__ __half g_Bd_lo[2][512 * 1024];
__device__ __half g_Bq_hi[2][512 * 512];
__device__ __half g_Bq_lo[2][512 * 512];
__device__ float g_biasP[2][FEAT];
__device__ float g_biasD[2][FEAT];
__device__ float g_rawd[(size_t)NNODE * FEAT];
__device__ float g_rawp[(size_t)NNODE * FEAT];
__device__ float g_bnstat[4 * FEAT];
__device__ int   g_cnt[4 * NNODE];
__device__ int   g_cur[4 * NNODE];
__device__ int   g_off[4 * (NNODE + 1)];
__device__ int   g_adj[4 * EMAX];

// ================= PTX helpers =================
__device__ __forceinline__ uint32_t smem_to_u32(const void* p) {
    uint32_t a;
    asm("{ .reg .u64 t; cvta.to.shared.u64 t, %1; cvt.u32.u64 %0, t; }" : "=r"(a) : "l"(p));
    return a;
}
__device__ __forceinline__ uint32_t elect_one_pred() {
    uint32_t pred;
    asm volatile("{\n\t.reg .pred p;\n\telect.sync _|p, 0xFFFFFFFF;\n\tselp.b32 %0, 1, 0, p;\n\t}" : "=r"(pred));
    return pred;
}
#define SMEM_SWIZZLE_64B(o) ((o) ^ (((o) >> 3) & 0x30))
static constexpr uint64_t SMEM_DESC_BASE_SW64 =
    (uint64_t(4) << 61) | (uint64_t(1) << 46) | (uint64_t(32) << 32) | (uint64_t(1) << 16);
#define MAKE_SMEM_DESC64(base) (SMEM_DESC_BASE_SW64 | ((uint64_t)((base) >> 4) & 0x3FFF))

#define CP_ASYNC16(dst, src) \
    asm volatile("cp.async.cg.shared.global [%0], [%1], 16;" :: "r"(dst), "l"(src) : "memory")
#define CP_COMMIT() asm volatile("cp.async.commit_group;" ::: "memory")
#define CP_WAIT2() asm volatile("cp.async.wait_group 2;" ::: "memory")
#define CP_WAIT1() asm volatile("cp.async.wait_group 1;" ::: "memory")
#define CP_WAIT0() asm volatile("cp.async.wait_group 0;" ::: "memory")

#if HAS_TCGEN05
#define TCGEN05_ALLOC(sm, n) \
    asm volatile("tcgen05.alloc.cta_group::1.sync.aligned.shared::cta.b32 [%0], %1;" \
                 :: "r"((uint32_t)(sm)), "r"((uint32_t)(n)) : "memory")
#define TCGEN05_DEALLOC(t, n) \
    asm volatile("tcgen05.dealloc.cta_group::1.sync.aligned.b32 %0, %1;" :: "r"(t), "r"((uint32_t)(n)))
#define TCGEN05_RELINQ() \
    asm volatile("tcgen05.relinquish_alloc_permit.cta_group::1.sync.aligned;")
#define TCGEN05_COMMIT(mb) \
    asm volatile("tcgen05.commit.cta_group::1.mbarrier::arrive::one.shared::cluster.b64 [%0];" \
                 :: "r"((uint32_t)(mb)) : "memory")
#define TCGEN05_WAIT_LD()  asm volatile("tcgen05.wait::ld.sync.aligned;" ::: "memory")
#define TCGEN05_FENCE_BEFORE() asm volatile("tcgen05.fence::before_thread_sync;" ::: "memory")
#define TCGEN05_FENCE_AFTER()  asm volatile("tcgen05.fence::after_thread_sync;" ::: "memory")
#define FENCE_ASYNC_SHARED() asm volatile("fence.proxy.async.shared::cta;" ::: "memory")
#define MBARRIER_INIT(mb, c) \
    asm volatile("mbarrier.init.shared.b64 [%0], %1;" :: "r"((uint32_t)(mb)), "r"((uint32_t)(c)) : "memory")
#define MBARRIER_INVAL(mb) \
    asm volatile("mbarrier.inval.shared.b64 [%0];" :: "r"((uint32_t)(mb)) : "memory")
#define MBARRIER_WAIT_PARITY(mb, ph) do { \
    uint32_t _mb = (uint32_t)(mb), _ph = (uint32_t)(ph), _done; \
    asm volatile("{\n\t.reg .pred p;\n\tmbarrier.try_wait.parity.acquire.cta.shared::cta.b64 p, [%1], %2;\n\tselp.b32 %0, 1, 0, p;\n\t}" \
        : "=r"(_done) : "r"(_mb), "r"(_ph) : "memory"); \
    if (!_done) { \
        asm volatile("{\n\t.reg .pred P1;\n\tWL_%=: \n\tmbarrier.try_wait.parity.acquire.cta.shared::cta.b64 P1, [%0], %1, 0x989680;\n\t@P1 bra.uni WD_%=;\n\tbra.uni WL_%=;\n\tWD_%=: \n\t}" \
            :: "r"(_mb), "r"(_ph) : "memory"); \
    } \
} while (0)

#define TCGEN05_LD_X32(r, addr) \
    asm volatile("tcgen05.ld.sync.aligned.32x32b.x32.b32 " \
        "{%0, %1, %2, %3, %4, %5, %6, %7, %8, %9, %10, %11, %12, %13, %14, %15, " \
        " %16, %17, %18, %19, %20, %21, %22, %23, %24, %25, %26, %27, %28, %29, %30, %31}, [%32];" \
        : "=r"((r)[0]), "=r"((r)[1]), "=r"((r)[2]), "=r"((r)[3]), "=r"((r)[4]), "=r"((r)[5]), "=r"((r)[6]), "=r"((r)[7]), \
          "=r"((r)[8]), "=r"((r)[9]), "=r"((r)[10]), "=r"((r)[11]), "=r"((r)[12]), "=r"((r)[13]), "=r"((r)[14]), "=r"((r)[15]), \
          "=r"((r)[16]), "=r"((r)[17]), "=r"((r)[18]), "=r"((r)[19]), "=r"((r)[20]), "=r"((r)[21]), "=r"((r)[22]), "=r"((r)[23]), \
          "=r"((r)[24]), "=r"((r)[25]), "=r"((r)[26]), "=r"((r)[27]), "=r"((r)[28]), "=r"((r)[29]), "=r"((r)[30]), "=r"((r)[31]) \
        : "r"(addr))

__device__ __forceinline__ void mma_f16_ss(uint32_t d_tmem, uint64_t a_desc, uint64_t b_desc,
                                           uint32_t idesc, uint32_t enable) {
    asm volatile(
        "{\n\t.reg .pred p;\n\tsetp.ne.u32 p, %5, 0;\n\t"
        "tcgen05.mma.cta_group::1.kind::f16 [%0], %1, %2, %3, {%4, %4, %4, %4}, p;\n\t}"
        :: "r"(d_tmem), "l"(a_desc), "l"(b_desc), "r"(idesc), "r"(0u), "r"(enable)
        : "memory");
}
#endif // HAS_TCGEN05

__device__ __forceinline__ void splith(float v, __half& h, __half& l) {
    h = __float2half_rn(v);
    l = __float2half_rn(v - __half2float(h));
}

// ================= CSR build =================
__global__ void zero_cnt_kernel() {
    int i = blockIdx.x * blockDim.x + threadIdx.x;
    if (i < 4 * NNODE) g_cnt[i] = 0;
}
__global__ void hist_kernel(const int* __restrict__ a_src, const int* __restrict__ a_dst,
                            const int* __restrict__ i_src, const int* __restrict__ i_dst, int E) {
    int i = blockIdx.x * blockDim.x + threadIdx.x;
    if (i >= 4 * E) return;
    int w = i / E, e = i - w * E;
    int k = (w == 0) ? a_dst[e] : (w == 1) ? a_src[e] : (w == 2) ? i_dst[e] : i_src[e];
    atomicAdd(&g_cnt[w * NNODE + k], 1);
}
__global__ void scan_kernel() {
    int c = blockIdx.x;
    __shared__ int sh[1024];
    __shared__ int carry_sh;
    int tid = threadIdx.x;
    if (tid == 0) { carry_sh = 0; g_off[c * (NNODE + 1)] = 0; }
    __syncthreads();
    for (int base = 0; base < NNODE; base += 1024) {
        int i = base + tid;
        int v = (i < NNODE) ? g_cnt[c * NNODE + i] : 0;
        sh[tid] = v;
        __syncthreads();
        #pragma unroll
        for (int d = 1; d < 1024; d <<= 1) {
            int t = (tid >= d) ? sh[tid - d] : 0;
            __syncthreads();
            sh[tid] += t;
            __syncthreads();
        }
        int incl = sh[tid];
        int carry = carry_sh;
        __syncthreads();
        if (i < NNODE) {
            g_off[c * (NNODE + 1) + i + 1] = carry + incl;
            g_cur[c * NNODE + i] = carry + incl - v;
        }
        if (tid == 1023) carry_sh = carry + sh[1023];
        __syncthreads();
    }
}
__global__ void fill_kernel(const int* __restrict__ a_src, const int* __restrict__ a_dst,
                            const int* __restrict__ i_src, const int* __restrict__ i_dst, int E) {
    int i = blockIdx.x * blockDim.x + threadIdx.x;
    if (i >= 4 * E) return;
    int w = i / E, e = i - w * E;
    int k = (w == 0) ? a_dst[e] : (w == 1) ? a_src[e] : (w == 2) ? i_dst[e] : i_src[e];
    int v = (w == 0) ? a_src[e] : (w == 1) ? a_dst[e] : (w == 2) ? i_src[e] : i_dst[e];
    int pos = atomicAdd(&g_cur[w * NNODE + k], 1);
    g_adj[w * E + pos] = v;
}

// ========== fused 4-way segment-mean gather; sources = fp16 self slots of A ==========
__global__ void gather4_kernel(const __half* __restrict__ Ad, __half* __restrict__ Ap, int E) {
    int c = blockIdx.y;
    const __half* src;
    __half* dst;
    int slda, dlda, coff;
    if (c == 0) { src = Ad; slda = 1024; dst = Ap; dlda = 2048; coff = 512; }
    else if (c == 1) { src = Ap; slda = 2048; dst = (__half*)Ad; dlda = 1024; coff = 512; }
    else { src = Ap; slda = 2048; dst = Ap; dlda = 2048; coff = (c == 2) ? 1024 : 1536; }
    int n = blockIdx.x;
    int t = threadIdx.x;            // 0..63, 8 halves each (16B)
    int s = g_off[c * (NNODE + 1) + n];
    int e = g_off[c * (NNODE + 1) + n + 1];
    const int* adj = g_adj + (size_t)c * E;
    float acc[8] = {0.f, 0.f, 0.f, 0.f, 0.f, 0.f, 0.f, 0.f};
    int j = s;
    for (; j + 3 < e; j += 4) {
        int r0 = adj[j], r1 = adj[j + 1], r2 = adj[j + 2], r3 = adj[j + 3];
        uint4 v0 = *(const uint4*)(src + (size_t)r0 * slda + t * 8);
        uint4 v1 = *(const uint4*)(src + (size_t)r1 * slda + t * 8);
        uint4 v2 = *(const uint4*)(src + (size_t)r2 * slda + t * 8);
        uint4 v3 = *(const uint4*)(src + (size_t)r3 * slda + t * 8);
        const uint4* vs[4] = {&v0, &v1, &v2, &v3};
        #pragma unroll
        for (int q = 0; q < 4; q++) {
            const __half2* h2 = (const __half2*)vs[q];
            #pragma unroll
            for (int p = 0; p < 4; p++) {
                float2 f = __half22float2(h2[p]);
                acc[2 * p] += f.x; acc[2 * p + 1] += f.y;
            }
        }
    }
    for (; j < e; j++) {
        int r0 = adj[j];
        uint4 v0 = *(const uint4*)(src + (size_t)r0 * slda + t * 8);
        const __half2* h2 = (const __half2*)&v0;
        #pragma unroll
        for (int p = 0; p < 4; p++) {
            float2 f = __half22float2(h2[p]);
            acc[2 * p] += f.x; acc[2 * p + 1] += f.y;
        }
    }
    float inv = (e > s) ? 1.0f / (float)(e - s) : 0.0f;
    __half o8[8];
    #pragma unroll
    for (int q = 0; q < 8; q++) o8[q] = __float2half_rn(acc[q] * inv);
    *(uint4*)(dst + (size_t)n * dlda + coff + t * 8) = *(uint4*)&o8[0];
}

// ========== merged fp32->fp16 input conversion into A self slots ==========
__global__ void split2_kernel(const float* __restrict__ h_p, const float* __restrict__ h_d,
                              __half* __restrict__ Ap, __half* __restrict__ Ad) {
    size_t idx = (size_t)blockIdx.x * blockDim.x + threadIdx.x;
    if (idx >= (size_t)NNODE * FEAT) return;
    int row = (int)(idx >> 9), col = (int)(idx & 511);
    const float* src = blockIdx.y ? h_d : h_p;
    __half* A = blockIdx.y ? Ad : Ap;
    int lda = blockIdx.y ? 1024 : 2048;
    A[(size_t)row * lda + col] = __float2half_rn(src[idx]);
}

// ========== weight prep: tiled transpose + fuse + fp16 split ==========
// grid (16, 16, 6), block (32, 32)
__global__ void wprep_kernel(const float* __restrict__ Ws1, const float* __restrict__ Wn1,
                             const float* __restrict__ Ws2, const float* __restrict__ Wn2,
                             const float* __restrict__ pWd, const float* __restrict__ pWp) {
    __shared__ float tile[4][32][33];
    int which = blockIdx.z;
    int n0 = blockIdx.x * 32, k0 = blockIdx.y * 32;
    int tx = threadIdx.x, ty = threadIdx.y;
    int srcIdx = (k0 + ty) * 512 + (n0 + tx);
    int nslots;
    __half *Bh, *Bl;
    int ldb;
    if (which == 0 || which == 2) {
        int li = which >> 1;
        const float* Ws = li ? Ws2 : Ws1;
        const float* Wn = li ? Wn2 : Wn1;
        tile[0][ty][tx] = Ws[srcIdx] + Ws[2 * FF + srcIdx] + Ws[3 * FF + srcIdx];
        tile[1][ty][tx] = Wn[srcIdx];
        tile[2][ty][tx] = Wn[2 * FF + srcIdx];
        tile[3][ty][tx] = Wn[3 * FF + srcIdx];
        nslots = 4; Bh = g_Bp_hi[li]; Bl = g_Bp_lo[li]; ldb = 2048;
    } else if (which == 1 || which == 3) {
        int li = which >> 1;
        const float* Ws = li ? Ws2 : Ws1;
        const float* Wn = li ? Wn2 : Wn1;
        tile[0][ty][tx] = Ws[FF + srcIdx];
        tile[1][ty][tx] = Wn[FF + srcIdx];
        nslots = 2; Bh = g_Bd_hi[li]; Bl = g_Bd_lo[li]; ldb = 1024;
    } else {
        int q = which - 4;
        const float* W = q ? pWp : pWd;
        tile[0][ty][tx] = W[srcIdx];
        nslots = 1; Bh = g_Bq_hi[q]; Bl = g_Bq_lo[q]; ldb = 512;
    }
    __syncthreads();
    // write transposed: n = n0+ty, k = k0+tx (contiguous in k)
    for (int sl = 0; sl < nslots; sl++) {
        float v = tile[sl][tx][ty];
        __half h, l;
        splith(v, h, l);
        size_t o = (size_t)(n0 + ty) * ldb + sl * 512 + k0 + tx;
        Bh[o] = h; Bl[o] = l;
    }
}
__global__ void bias_kernel(const float* __restrict__ b1, const float* __restrict__ b2) {
    int i = threadIdx.x;
    g_biasP[0][i] = b1[i] + b1[1024 + i] + b1[1536 + i];
    g_biasD[0][i] = b1[512 + i];
    g_biasP[1][i] = b2[i] + b2[1024 + i] + b2[1536 + i];
    g_biasD[1][i] = b2[512 + i];
}

// ================= paired tcgen05 fp16 GEMM, M=256 x N=256, KC=32, 3-stage pipeline =====
// C = A16 * (Bh + Bl), fp32 TMEM accum, + bias
struct GPair {
    const __half *A0, *Bh0, *Bl0; const float* bias0; float* C0; int lda0, ldb0, K0;
    const __half *A1, *Bh1, *Bl1; const float* bias1; float* C1; int lda1, ldb1, K1;
};
#define STAGE_BYTES 49152   // A 16K | Bh 16K | Bl 16K
#define GEMM_SMEM (1024 + 3 * STAGE_BYTES)
__global__ __launch_bounds__(128)
void mma_gemm_pair(const GPair gp, int M) {
    const __half* A   = blockIdx.z ? gp.A1 : gp.A0;
    const __half* Bhi = blockIdx.z ? gp.Bh1 : gp.Bh0;
    const __half* Blo = blockIdx.z ? gp.Bl1 : gp.Bl0;
    const float* bias = blockIdx.z ? gp.bias1 : gp.bias0;
    float* C = blockIdx.z ? gp.C1 : gp.C0;
    const int lda = blockIdx.z ? gp.lda1 : gp.lda0;
    const int ldb = blockIdx.z ? gp.ldb1 : gp.ldb0;
    const int Ktot = blockIdx.z ? gp.K1 : gp.K0;
#if HAS_TCGEN05
    extern __shared__ char smem[];
    uint32_t sb = smem_to_u32(smem);
    const int tid = threadIdx.x;
    const int wid = tid >> 5, lid = tid & 31;
    const int m0 = blockIdx.y * 256, n0 = blockIdx.x * 256;

    if (wid == 0) { TCGEN05_ALLOC(sb, 512); TCGEN05_RELINQ(); }
    if (tid == 0) MBARRIER_INIT(sb + 8, 1);
    __syncthreads();
    uint32_t tbase;
    asm volatile("ld.shared.b32 %0, [%1];" : "=r"(tbase) : "r"(sb));

    const uint32_t idesc = 0x8400010u;   // F32 acc, F16 A/B, M=128, N=256
    const int nst = Ktot >> 5;           // KC = 32

    auto issue_loads = [&](int s) {
        int k0 = s << 5;
        uint32_t base = sb + 1024 + (uint32_t)(s % 3) * STAGE_BYTES;
        // each tile: 256 rows x 64B = 1024 16B-chunks; 8 per thread per tile
        #pragma unroll
        for (int c = 0; c < 8; c++) {
            int chunk = c * 128 + tid;
            int row = chunk >> 2, ch = chunk & 3;
            uint32_t sw = SMEM_SWIZZLE_64B((uint32_t)(row * 64 + ch * 16));
            size_t ga = (size_t)(m0 + row) * lda + k0 + ch * 8;
            size_t gb = (size_t)(n0 + row) * ldb + k0 + ch * 8;
            CP_ASYNC16(base + sw, A + ga);
            CP_ASYNC16(base + 16384 + sw, Bhi + gb);
            CP_ASYNC16(base + 32768 + sw, Blo + gb);
        }
        CP_COMMIT();
    };

    issue_loads(0);
    issue_loads(1);
    for (int s = 0; s < nst; s++) {
        if (s >= 1) MBARRIER_WAIT_PARITY(sb + 8, (s - 1) & 1);
        if (s + 2 < nst)      { issue_loads(s + 2); CP_WAIT2(); }
        else if (s + 1 < nst) { CP_WAIT1(); }
        else                  { CP_WAIT0(); }
        __syncthreads();
        FENCE_ASYNC_SHARED();
        if (wid == 0 && elect_one_pred()) {
            uint32_t bufb = sb + 1024 + (uint32_t)(s % 3) * STAGE_BYTES;
            uint64_t dA0 = MAKE_SMEM_DESC64(bufb);
            uint64_t dA1 = MAKE_SMEM_DESC64(bufb + 8192);
            uint64_t dBh = MAKE_SMEM_DESC64(bufb + 16384);
            uint64_t dBl = MAKE_SMEM_DESC64(bufb + 32768);
            #pragma unroll
            for (int kk = 0; kk < 2; kk++) {
                uint64_t o = (uint64_t)(kk * 2);
                uint32_t en0 = !(s == 0 && kk == 0);
                mma_f16_ss(tbase,       dA0 + o, dBh + o, idesc, en0);
                mma_f16_ss(tbase + 256, dA1 + o, dBh + o, idesc, en0);
                mma_f16_ss(tbase,       dA0 + o, dBl + o, idesc, 1u);
                mma_f16_ss(tbase + 256, dA1 + o, dBl + o, idesc, 1u);
            }
            TCGEN05_COMMIT(sb + 8);
        }
    }
    MBARRIER_WAIT_PARITY(sb + 8, (nst - 1) & 1);
    TCGEN05_FENCE_AFTER();

    #pragma unroll
    for (int half = 0; half < 2; half++) {
        int gr = m0 + half * 128 + wid * 32 + lid;
        uint32_t dt = tbase + half * 256;
        #pragma unroll
        for (int base = 0; base < 256; base += 32) {
            uint32_t r[32];
            TCGEN05_LD_X32(r, dt + base);
            TCGEN05_WAIT_LD();
            if (gr < M) {
                float* cp = C + (size_t)gr * 512 + n0 + base;
                #pragma unroll
                for (int j = 0; j < 32; j += 4) {
                    float4 v;
                    v.x = __uint_as_float(r[j + 0]) + bias[n0 + base + j + 0];
                    v.y = __uint_as_float(r[j + 1]) + bias[n0 + base + j + 1];
                    v.z = __uint_as_float(r[j + 2]) + bias[n0 + base + j + 2];
                    v.w = __uint_as_float(r[j + 3]) + bias[n0 + base + j + 3];
                    *(float4*)(cp + j) = v;
                }
            }
        }
    }
    TCGEN05_FENCE_BEFORE();
    __syncthreads();
    if (tid == 0) MBARRIER_INVAL(sb + 8);
    __syncthreads();
    if (wid == 0) TCGEN05_DEALLOC(tbase, 512);
#else
    const int tid = threadIdx.x;
    const int m0 = blockIdx.y * 256, n0 = blockIdx.x * 256;
    for (int rc = tid; rc < 256 * 256; rc += blockDim.x) {
        int r = rc >> 8, c = rc & 255;
        int gr = m0 + r, gc = n0 + c;
        if (gr >= M) continue;
        const __half* a  = A + (size_t)gr * lda;
        const __half* bh = Bhi + (size_t)gc * ldb;
        const __half* bl = Blo + (size_t)gc * ldb;
        float acc = 0.f;
        for (int k = 0; k < Ktot; k++) {
            float av = __half2float(a[k]);
            acc += av * __half2float(bh[k]) + av * __half2float(bl[k]);
        }
        C[(size_t)gr * 512 + gc] = acc + bias[gc];
    }
#endif
}

// ================= BatchNorm + ReLU (merged d+p) =================
__global__ void zero_stats_kernel() {
    int i = blockIdx.x * blockDim.x + threadIdx.x;
    if (i < 4 * FEAT) g_bnstat[i] = 0.f;
}
__global__ void bn_reduce2_kernel(const float* __restrict__ xd, const float* __restrict__ xp) {
    int gcol = blockIdx.x * 256 + threadIdx.x;   // 0..1023
    int isP = gcol >= 512;
    int col = gcol & 511;
    const float* x = isP ? xp : xd;
    float s = 0.f, s2 = 0.f;
    for (int r = blockIdx.y; r < NNODE; r += gridDim.y) {
        float v = x[(size_t)r * FEAT + col];
        s += v; s2 += v * v;
    }
    int base = isP ? 1024 : 0;
    atomicAdd(&g_bnstat[base + col], s);
    atomicAdd(&g_bnstat[base + 512 + col], s2);
}
__global__ void bn_norm2_kernel(const float* __restrict__ rawd, const float* __restrict__ rawp,
                                __half* __restrict__ Ad, __half* __restrict__ Ap,
                                const float* __restrict__ gamma_l, const float* __restrict__ beta_l) {
    size_t idx = (size_t)blockIdx.x * blockDim.x + threadIdx.x;
    if (idx >= (size_t)NNODE * FEAT) return;
    int isP = blockIdx.y;
    int col = (int)(idx & (FEAT - 1));
    int row = (int)(idx >> 9);
    const float* raw = isP ? rawp : rawd;
    __half* Ax = isP ? Ap : Ad;
    int lda = isP ? 2048 : 1024;
    int sbase = isP ? 1024 : 0;
    const float* gamma = gamma_l + isP * FEAT;
    const float* beta  = beta_l + isP * FEAT;
    float mean = g_bnstat[sbase + col] * (1.0f / NNODE);
    float var  = g_bnstat[sbase + 512 + col] * (1.0f / NNODE) - mean * mean;
    float sc = gamma[col] * rsqrtf(var + BN_EPS);
    float v = (raw[idx] - mean) * sc + beta[col];
    v = v > 0.f ? v : 0.f;
    Ax[(size_t)row * lda + col] = __float2half_rn(v);
}

// ================= host orchestration =================
extern "C" void kernel_launch(void* const* d_in, const int* in_sizes, int n_in,
                              void* d_out, int out_size) {
    const float* h_d  = (const float*)d_in[0];
    const float* h_p  = (const float*)d_in[1];
    const float* Ws1  = (const float*)d_in[2];
    const float* Wn1  = (const float*)d_in[3];
    const float* b1   = (const float*)d_in[4];
    const float* Ws2  = (const float*)d_in[5];
    const float* Wn2  = (const float*)d_in[6];
    const float* b2   = (const float*)d_in[7];
    const float* gam  = (const float*)d_in[8];
    const float* bet  = (const float*)d_in[9];
    const float* pWd  = (const float*)d_in[10];
    const float* pbd  = (const float*)d_in[11];
    const float* pWp  = (const float*)d_in[12];
    const float* pbp  = (const float*)d_in[13];
    const int* a_src = (const int*)d_in[14];
    const int* a_dst = (const int*)d_in[15];
    const int* i_src = (const int*)d_in[16];
    const int* i_dst = (const int*)d_in[17];
    int E = in_sizes[14];

    float* out_d = (float*)d_out;
    float* out_p = out_d + (size_t)NNODE * FEAT;

    __half *Ap, *Ad, *BpH, *BpL, *BdH, *BdL, *BqH, *BqL;
    float *rawd, *rawp, *biasP, *biasD;
    cudaGetSymbolAddress((void**)&Ap, g_Ap);
    cudaGetSymbolAddress((void**)&Ad, g_Ad);
    cudaGetSymbolAddress((void**)&BpH, g_Bp_hi);
    cudaGetSymbolAddress((void**)&BpL, g_Bp_lo);
    cudaGetSymbolAddress((void**)&BdH, g_Bd_hi);
    cudaGetSymbolAddress((void**)&BdL, g_Bd_lo);
    cudaGetSymbolAddress((void**)&BqH, g_Bq_hi);
    cudaGetSymbolAddress((void**)&BqL, g_Bq_lo);
    cudaGetSymbolAddress((void**)&rawd, g_rawd);
    cudaGetSymbolAddress((void**)&rawp, g_rawp);
    cudaGetSymbolAddress((void**)&biasP, g_biasP);
    cudaGetSymbolAddress((void**)&biasD, g_biasD);

    cudaFuncSetAttribute(mma_gemm_pair, cudaFuncAttributeMaxDynamicSharedMemorySize, GEMM_SMEM);

    const int NW = (NNODE * FEAT + 255) / 256;
    const int MT = (NNODE + 255) / 256;               // 79
    const dim3 gpair(2, MT, 2);
    const dim3 g4(NNODE, 4);

    GPair lay[2];
    for (int li = 0; li < 2; li++) {
        lay[li].A0 = Ap;
        lay[li].Bh0 = BpH + (size_t)li * 512 * 2048; lay[li].Bl0 = BpL + (size_t)li * 512 * 2048;
        lay[li].bias0 = biasP + li * FEAT; lay[li].C0 = rawp;
        lay[li].lda0 = 2048; lay[li].ldb0 = 2048; lay[li].K0 = 2048;
        lay[li].A1 = Ad;
        lay[li].Bh1 = BdH + (size_t)li * 512 * 1024; lay[li].Bl1 = BdL + (size_t)li * 512 * 1024;
        lay[li].bias1 = biasD + li * FEAT; lay[li].C1 = rawd;
        lay[li].lda1 = 1024; lay[li].ldb1 = 1024; lay[li].K1 = 1024;
    }
    GPair proj;
    proj.A0 = Ad; proj.Bh0 = BqH; proj.Bl0 = BqL;
    proj.bias0 = pbd; proj.C0 = out_d; proj.lda0 = 1024; proj.ldb0 = 512; proj.K0 = 512;
    proj.A1 = Ap; proj.Bh1 = BqH + FF; proj.Bl1 = BqL + FF;
    proj.bias1 = pbp; proj.C1 = out_p; proj.lda1 = 2048; proj.ldb1 = 512; proj.K1 = 512;

    // ---- prep ----
    wprep_kernel<<<dim3(16, 16, 6), dim3(32, 32)>>>(Ws1, Wn1, Ws2, Wn2, pWd, pWp);
    bias_kernel<<<1, 512>>>(b1, b2);
    split2_kernel<<<dim3(NW, 2), 256>>>(h_p, h_d, Ap, Ad);

    // ---- CSR build ----
    zero_cnt_kernel<<<(4 * NNODE + 255) / 256, 256>>>();
    hist_kernel<<<(4 * E + 255) / 256, 256>>>(a_src, a_dst, i_src, i_dst, E);
    scan_kernel<<<4, 1024>>>();
    fill_kernel<<<(4 * E + 255) / 256, 256>>>(a_src, a_dst, i_src, i_dst, E);

    // ---- layers ----
    for (int li = 0; li < 2; li++) {
        gather4_kernel<<<g4, 64>>>(Ad, Ap, E);
        mma_gemm_pair<<<gpair, 128, GEMM_SMEM>>>(lay[li], NNODE);
        zero_stats_kernel<<<8, 256>>>();
        bn_reduce2_kernel<<<dim3(4, 64), 256>>>(rawd, rawp);
        bn_norm2_kernel<<<dim3(NW, 2), 256>>>(rawd, rawp, Ad, Ap,
                                              gam + li * 2 * FEAT, bet + li * 2 * FEAT);
    }

    // ---- projections ----
    mma_gemm_pair<<<gpair, 128, GEMM_SMEM>>>(proj, NNODE);
}